// round 1
// baseline (speedup 1.0000x reference)
#include <cuda_runtime.h>
#include <math.h>

#define B_    16
#define H_    512
#define W_    512
#define HW_   (H_ * W_)
#define NPIX_ (B_ * HW_)
#define CH_   3

// Scratch (allocation-free: __device__ globals)
__device__ float         g_rsr[NPIX_];      // 16.8 MB
__device__ unsigned char g_gate[NPIX_];     //  4.2 MB
__device__ double        g_sum[B_];
__device__ double        g_sumsq[B_];
__device__ float         g_pw[B_];
__device__ double        g_acc;

__device__ __forceinline__ float warpReduce(float v) {
    #pragma unroll
    for (int o = 16; o; o >>= 1) v += __shfl_down_sync(0xffffffffu, v, o);
    return v;
}

__global__ void k_zero() {
    int i = threadIdx.x;
    if (i < B_) { g_sum[i] = 0.0; g_sumsq[i] = 0.0; }
    if (i == 0) g_acc = 0.0;
}

// One thread per (b,h,w) pixel: channel-sum abs residuals, gate byte,
// per-image sum / sum-of-squares for the global variance.
__global__ void k_residual(const float* __restrict__ outp,
                           const float* __restrict__ emap,
                           const float* __restrict__ gtp) {
    int idx = blockIdx.x * blockDim.x + threadIdx.x;   // [0, NPIX_)
    int b = idx / HW_;
    int p = idx - b * HW_;
    size_t base = (size_t)b * CH_ * HW_ + p;
    float rs = 0.f, re = 0.f;
    #pragma unroll
    for (int c = 0; c < CH_; c++) {
        float g = gtp[base + (size_t)c * HW_];
        rs += fabsf(g - outp[base + (size_t)c * HW_]);
        re += fabsf(g - emap[base + (size_t)c * HW_]);
    }
    g_rsr[idx]  = rs;
    g_gate[idx] = (rs < re) ? 0 : 1;

    // block reduction (HW_ % 256 == 0 so each block is within one image)
    float s = warpReduce(rs);
    float q = warpReduce(rs * rs);
    __shared__ float sh_s[8], sh_q[8];
    int lane = threadIdx.x & 31, w = threadIdx.x >> 5;
    if (lane == 0) { sh_s[w] = s; sh_q[w] = q; }
    __syncthreads();
    if (w == 0) {
        s = (lane < 8) ? sh_s[lane] : 0.f;
        q = (lane < 8) ? sh_q[lane] : 0.f;
        s = warpReduce(s);
        q = warpReduce(q);
        if (lane == 0) {
            atomicAdd(&g_sum[b],   (double)s);
            atomicAdd(&g_sumsq[b], (double)q);
        }
    }
}

__global__ void k_patch() {
    int b = threadIdx.x;
    if (b >= B_) return;
    double n   = (double)HW_;
    double var = (g_sumsq[b] - g_sum[b] * g_sum[b] / n) / (n - 1.0);
    g_pw[b] = (float)pow(var, 0.2);
}

__device__ __forceinline__ int refl(int i) {
    i = (i < 0) ? -i : i;
    return (i >= H_) ? (2 * (H_ - 1) - i) : i;   // H_ == W_
}

// Tiled 7x7 unbiased local variance (reflect pad) fused with gate, patch
// weight, and the final loss reduction. 32x32 outputs per block, 3-halo.
__global__ void k_localvar() {
    __shared__ float s_r [38][40];   // raw tile + halo (pad to 40 vs bank conflicts)
    __shared__ float s_hs[38][33];   // horizontal 7-sum
    __shared__ float s_hq[38][33];   // horizontal 7-sum of squares

    int b   = blockIdx.z;
    int ty0 = blockIdx.y * 32;
    int tx0 = blockIdx.x * 32;
    int tid = threadIdx.x;

    const float* rb = g_rsr + (size_t)b * HW_;

    for (int i = tid; i < 38 * 38; i += 256) {
        int lr = i / 38, lc = i - lr * 38;
        int gr = refl(ty0 + lr - 3), gc = refl(tx0 + lc - 3);
        s_r[lr][lc] = rb[gr * W_ + gc];
    }
    __syncthreads();

    for (int i = tid; i < 38 * 32; i += 256) {
        int r = i >> 5, c = i & 31;
        float s = 0.f, q = 0.f;
        #pragma unroll
        for (int d = 0; d < 7; d++) { float v = s_r[r][c + d]; s += v; q += v * v; }
        s_hs[r][c] = s;
        s_hq[r][c] = q;
    }
    __syncthreads();

    float pw  = g_pw[b];
    float acc = 0.f;
    for (int i = tid; i < 32 * 32; i += 256) {
        int r = i >> 5, c = i & 31;
        float s = 0.f, q = 0.f;
        #pragma unroll
        for (int d = 0; d < 7; d++) { s += s_hs[r + d][c]; q += s_hq[r + d][c]; }
        float var = (q - s * s * (1.f / 49.f)) * (1.f / 48.f);
        int   idx = b * HW_ + (ty0 + r) * W_ + (tx0 + c);
        float rs  = s_r[r + 3][c + 3];
        if (g_gate[idx]) acc += fabsf(pw * var * rs);
    }

    acc = warpReduce(acc);
    __shared__ float sh[8];
    int lane = tid & 31, w = tid >> 5;
    if (lane == 0) sh[w] = acc;
    __syncthreads();
    if (w == 0) {
        acc = (lane < 8) ? sh[lane] : 0.f;
        acc = warpReduce(acc);
        if (lane == 0) atomicAdd(&g_acc, (double)acc);
    }
}

__global__ void k_final(float* out) {
    out[0] = (float)(g_acc / (double)((long long)NPIX_ * CH_));
}

extern "C" void kernel_launch(void* const* d_in, const int* in_sizes, int n_in,
                              void* d_out, int out_size) {
    const float* outp = (const float*)d_in[0];
    const float* emap = (const float*)d_in[1];
    const float* gtp  = (const float*)d_in[2];
    float* out = (float*)d_out;

    k_zero<<<1, 32>>>();
    k_residual<<<NPIX_ / 256, 256>>>(outp, emap, gtp);
    k_patch<<<1, 16>>>();
    dim3 grid(W_ / 32, H_ / 32, B_);
    k_localvar<<<grid, 256>>>();
    k_final<<<1, 1>>>(out);
}